// round 7
// baseline (speedup 1.0000x reference)
#include <cuda_runtime.h>
#include <cuda_bf16.h>
#include <math.h>

#define NV   8192
#define IND  512
#define OUTD 256

// ---------------- device scratch (no runtime allocation allowed) ----------------
__device__ float          g_h[NV * OUTD];                    // 8 MB
__device__ unsigned short g_A2x[(size_t)NV * 1536];          // 24 MB  (xh | xh | xl) bf16 bits
__device__ unsigned short g_B2w[1536 * OUTD];                // 0.75 MB (wh ; wl ; wh) bf16 bits
__device__ float          g_s[NV];
__device__ float          g_E[NV];
__device__ float          g_Z[NV];
__device__ float          g_m[1];
__device__ unsigned       g_mask[(size_t)NV * 256];          // 8 MB bitmask of adj
__device__ unsigned short g_G2[(size_t)2 * NV * OUTD];       // 8 MB  rows 2j=hi(E*h), 2j+1=lo
__device__ float          g_outun[NV * OUTD];                // 8 MB

__device__ __forceinline__ unsigned short f2bf(float f) {
    return __bfloat16_as_ushort(__float2bfloat16_rn(f));
}
__device__ __forceinline__ float bf2f(unsigned short u) {
    return __bfloat162float(__ushort_as_bfloat16(u));
}

// ---------------- prep: split x into (hi|hi|lo) row blocks of A2x -----------------
__global__ void prep_x_kernel(const float* __restrict__ x, unsigned short* __restrict__ A2x) {
    int idx = blockIdx.x * 256 + threadIdx.x;           // 8192*128 threads, 4 elems each
    int row = idx >> 7;
    int c   = (idx & 127) << 2;
    float4 v = *(const float4*)(x + (size_t)row * IND + c);
    unsigned short h0 = f2bf(v.x), h1 = f2bf(v.y), h2 = f2bf(v.z), h3 = f2bf(v.w);
    unsigned short l0 = f2bf(v.x - bf2f(h0)), l1 = f2bf(v.y - bf2f(h1));
    unsigned short l2 = f2bf(v.z - bf2f(h2)), l3 = f2bf(v.w - bf2f(h3));
    uint2 hp = make_uint2((unsigned)h0 | ((unsigned)h1 << 16), (unsigned)h2 | ((unsigned)h3 << 16));
    uint2 lp = make_uint2((unsigned)l0 | ((unsigned)l1 << 16), (unsigned)l2 | ((unsigned)l3 << 16));
    unsigned short* base = A2x + (size_t)row * 1536;
    *(uint2*)(base + c)        = hp;
    *(uint2*)(base + 512 + c)  = hp;
    *(uint2*)(base + 1024 + c) = lp;
}

// ---------------- prep: W [256,512] -> B2w [1536,256] = (wh ; wl ; wh) ------------
__global__ void prep_w_kernel(const float* __restrict__ W, unsigned short* __restrict__ B2w) {
    int idx = blockIdx.x * 256 + threadIdx.x;           // 131072 threads
    int n = idx >> 9;
    int k = idx & 511;
    float f = W[idx];
    unsigned short hi = f2bf(f);
    unsigned short lo = f2bf(f - bf2f(hi));
    B2w[(size_t)k * 256 + n]          = hi;
    B2w[(size_t)(512 + k) * 256 + n]  = lo;
    B2w[(size_t)(1024 + k) * 256 + n] = hi;
}

// ---------------- shared bf16 MMA GEMM: C[M,256] += A[M,K] * B[K,256] -------------
// BM=128, BN=64, BK=64, 256 threads (8 warps, 4x2), warp tile 32x32, mma m16n8k16.
// FROM_BITS: A generated from bitmask (bit j -> k'=2j and 2j+1, value 1.0bf16).
template <bool FROM_BITS>
__global__ void __launch_bounds__(256, 2)
gemm_bf16_kernel(const unsigned short* __restrict__ Ag,
                 const unsigned* __restrict__ Abits,
                 const unsigned short* __restrict__ Bg,
                 float* __restrict__ C, int K)
{
    __shared__ __align__(16) unsigned short sA[128][72];
    __shared__ __align__(16) unsigned short sB[64][72];

    const int tid  = threadIdx.x;
    const int lane = tid & 31;
    const int warp = tid >> 5;
    const int wm = warp & 3;         // 4 warps along M (32 rows each)
    const int wn = warp >> 2;        // 2 warps along N (32 cols each)
    const int m0 = blockIdx.y * 128;
    const int n0 = blockIdx.x * 64;

    float acc[2][4][4];
#pragma unroll
    for (int i = 0; i < 2; i++)
#pragma unroll
        for (int j = 0; j < 4; j++)
#pragma unroll
            for (int k = 0; k < 4; k++) acc[i][j][k] = 0.f;

    const int nIter = K >> 6;
    const int rowA = tid >> 3, segA = tid & 7;   // staging indices
    const int ar = tid >> 1, ah = tid & 1;       // bit-expansion indices

    unsigned pw = 0;
    uint4 pa0, pa1, pa2, pa3, pb0, pb1;

    // ---- prefetch kb = 0 ----
    {
        if (FROM_BITS) {
            pw = Abits[(size_t)(m0 + ar) * (K >> 6) + 0];
        } else {
            pa0 = *(const uint4*)(Ag + (size_t)(m0 + rowA)      * K + segA * 8);
            pa1 = *(const uint4*)(Ag + (size_t)(m0 + rowA + 32) * K + segA * 8);
            pa2 = *(const uint4*)(Ag + (size_t)(m0 + rowA + 64) * K + segA * 8);
            pa3 = *(const uint4*)(Ag + (size_t)(m0 + rowA + 96) * K + segA * 8);
        }
        pb0 = *(const uint4*)(Bg + (size_t)(rowA)      * 256 + n0 + segA * 8);
        pb1 = *(const uint4*)(Bg + (size_t)(rowA + 32) * 256 + n0 + segA * 8);
    }

    for (int kb = 0; kb < nIter; kb++) {
        // ---- store stage (regs -> smem) ----
        if (FROM_BITS) {
            unsigned w = pw >> (ah * 16);
            uint4* dst = (uint4*)&sA[ar][ah * 32];
#pragma unroll
            for (int q = 0; q < 4; q++) {
                uint4 v;
                v.x = (w & 1u) ? 0x3F803F80u : 0u; w >>= 1;
                v.y = (w & 1u) ? 0x3F803F80u : 0u; w >>= 1;
                v.z = (w & 1u) ? 0x3F803F80u : 0u; w >>= 1;
                v.w = (w & 1u) ? 0x3F803F80u : 0u; w >>= 1;
                dst[q] = v;
            }
        } else {
            *(uint4*)&sA[rowA][segA * 8]      = pa0;
            *(uint4*)&sA[rowA + 32][segA * 8] = pa1;
            *(uint4*)&sA[rowA + 64][segA * 8] = pa2;
            *(uint4*)&sA[rowA + 96][segA * 8] = pa3;
        }
        *(uint4*)&sB[rowA][segA * 8]      = pb0;
        *(uint4*)&sB[rowA + 32][segA * 8] = pb1;
        __syncthreads();

        // ---- prefetch kb+1 (overlaps with compute) ----
        if (kb + 1 < nIter) {
            int kn = kb + 1;
            if (FROM_BITS) {
                pw = Abits[(size_t)(m0 + ar) * (K >> 6) + kn];
            } else {
                pa0 = *(const uint4*)(Ag + (size_t)(m0 + rowA)      * K + kn * 64 + segA * 8);
                pa1 = *(const uint4*)(Ag + (size_t)(m0 + rowA + 32) * K + kn * 64 + segA * 8);
                pa2 = *(const uint4*)(Ag + (size_t)(m0 + rowA + 64) * K + kn * 64 + segA * 8);
                pa3 = *(const uint4*)(Ag + (size_t)(m0 + rowA + 96) * K + kn * 64 + segA * 8);
            }
            pb0 = *(const uint4*)(Bg + (size_t)(kn * 64 + rowA)      * 256 + n0 + segA * 8);
            pb1 = *(const uint4*)(Bg + (size_t)(kn * 64 + rowA + 32) * 256 + n0 + segA * 8);
        }

        // ---- compute ----
#pragma unroll
        for (int kk = 0; kk < 4; kk++) {
            unsigned a[2][4];
#pragma unroll
            for (int mi = 0; mi < 2; mi++) {
                int row = wm * 32 + mi * 16 + (lane >> 2);
                int col = kk * 16 + (lane & 3) * 2;
                a[mi][0] = *(const unsigned*)&sA[row][col];
                a[mi][1] = *(const unsigned*)&sA[row + 8][col];
                a[mi][2] = *(const unsigned*)&sA[row][col + 8];
                a[mi][3] = *(const unsigned*)&sA[row + 8][col + 8];
            }
            unsigned b[4][2];
#pragma unroll
            for (int ni = 0; ni < 4; ni++) {
                unsigned saddr = (unsigned)__cvta_generic_to_shared(
                    &sB[kk * 16 + (lane & 15)][wn * 32 + ni * 8]);
                asm volatile(
                    "ldmatrix.sync.aligned.m8n8.x2.trans.shared.b16 {%0,%1}, [%2];"
                    : "=r"(b[ni][0]), "=r"(b[ni][1]) : "r"(saddr));
            }
#pragma unroll
            for (int mi = 0; mi < 2; mi++)
#pragma unroll
                for (int ni = 0; ni < 4; ni++)
                    asm volatile(
                        "mma.sync.aligned.m16n8k16.row.col.f32.bf16.bf16.f32 "
                        "{%0,%1,%2,%3},{%4,%5,%6,%7},{%8,%9},{%0,%1,%2,%3};"
                        : "+f"(acc[mi][ni][0]), "+f"(acc[mi][ni][1]),
                          "+f"(acc[mi][ni][2]), "+f"(acc[mi][ni][3])
                        : "r"(a[mi][0]), "r"(a[mi][1]), "r"(a[mi][2]), "r"(a[mi][3]),
                          "r"(b[ni][0]), "r"(b[ni][1]));
        }
        __syncthreads();
    }

    // ---- epilogue ----
#pragma unroll
    for (int mi = 0; mi < 2; mi++) {
        int row = m0 + wm * 32 + mi * 16 + (lane >> 2);
#pragma unroll
        for (int ni = 0; ni < 4; ni++) {
            int col = n0 + wn * 32 + ni * 8 + (lane & 3) * 2;
            *(float2*)&C[(size_t)row * 256 + col]       = make_float2(acc[mi][ni][0], acc[mi][ni][1]);
            *(float2*)&C[(size_t)(row + 8) * 256 + col] = make_float2(acc[mi][ni][2], acc[mi][ni][3]);
        }
    }
}

// ---------------- s_j = h @ a[256:512] : one warp per row ------------------------
__global__ void s_kernel(const float* __restrict__ h, const float* __restrict__ a,
                         float* __restrict__ s) {
    int row  = blockIdx.x * 8 + (threadIdx.x >> 5);
    int lane = threadIdx.x & 31;
    const float* hr = h + (size_t)row * OUTD;
    const float* a2 = a + OUTD;
    float v = 0.f;
#pragma unroll
    for (int k = 0; k < 8; k++) v += hr[lane + 32 * k] * a2[lane + 32 * k];
#pragma unroll
    for (int off = 16; off; off >>= 1) v += __shfl_xor_sync(0xffffffffu, v, off);
    if (lane == 0) s[row] = v;
}

__global__ void max_kernel(const float* __restrict__ s, float* __restrict__ m) {
    __shared__ float red[1024];
    float v = -1e30f;
    for (int i = threadIdx.x; i < NV; i += 1024) v = fmaxf(v, s[i]);
    red[threadIdx.x] = v;
    __syncthreads();
    for (int st = 512; st; st >>= 1) {
        if (threadIdx.x < st) red[threadIdx.x] = fmaxf(red[threadIdx.x], red[threadIdx.x + st]);
        __syncthreads();
    }
    if (threadIdx.x == 0) *m = red[0];
}

// ---------------- E = exp(s-m); G2 rows 2j = bf16_hi(E*h), 2j+1 = bf16_lo ---------
__global__ void eg_kernel(const float* __restrict__ h, const float* __restrict__ s,
                          const float* __restrict__ m, float* __restrict__ E,
                          unsigned short* __restrict__ G2) {
    int idx = blockIdx.x * 256 + threadIdx.x;           // 8192*64 threads, 4 elems each
    int row = idx >> 6;
    int c   = (idx & 63) << 2;
    float e = expf(s[row] - *m);
    if ((idx & 63) == 0) E[row] = e;
    float4 hv = *(const float4*)(h + (size_t)row * OUTD + c);
    float g0 = e * hv.x, g1 = e * hv.y, g2 = e * hv.z, g3 = e * hv.w;
    unsigned short h0 = f2bf(g0), h1 = f2bf(g1), h2 = f2bf(g2), h3 = f2bf(g3);
    unsigned short l0 = f2bf(g0 - bf2f(h0)), l1 = f2bf(g1 - bf2f(h1));
    unsigned short l2 = f2bf(g2 - bf2f(h2)), l3 = f2bf(g3 - bf2f(h3));
    uint2 hp = make_uint2((unsigned)h0 | ((unsigned)h1 << 16), (unsigned)h2 | ((unsigned)h3 << 16));
    uint2 lp = make_uint2((unsigned)l0 | ((unsigned)l1 << 16), (unsigned)l2 | ((unsigned)l3 << 16));
    *(uint2*)(G2 + (size_t)(2 * row) * 256 + c)     = hp;
    *(uint2*)(G2 + (size_t)(2 * row + 1) * 256 + c) = lp;
}

// ---------------- per-row: bitmask, Z, alpha (adj read exactly once) --------------
__global__ void alpha_kernel(const int* __restrict__ adj, const float* __restrict__ E,
                             unsigned* __restrict__ mask, float* __restrict__ Z,
                             float* __restrict__ alpha, int writeAlpha) {
    __shared__ unsigned sw[256];
    __shared__ float red[256];
    __shared__ float sInv;
    const int i = blockIdx.x, t = threadIdx.x;
    const int4* row4 = (const int4*)(adj + (size_t)i * NV);
    float z = 0.f;
    unsigned w = 0;
    const int base = t * 8;                              // this thread owns j in [t*32, t*32+32)
#pragma unroll
    for (int q = 0; q < 8; q++) {
        int4 v = row4[base + q];
        float4 e4 = *(const float4*)(E + t * 32 + q * 4);
        if (v.x) { z += e4.x; w |= 1u << (q * 4 + 0); }
        if (v.y) { z += e4.y; w |= 1u << (q * 4 + 1); }
        if (v.z) { z += e4.z; w |= 1u << (q * 4 + 2); }
        if (v.w) { z += e4.w; w |= 1u << (q * 4 + 3); }
    }
    sw[t] = w;
    mask[(size_t)i * 256 + t] = w;
    red[t] = z;
    __syncthreads();
    for (int st = 128; st; st >>= 1) {
        if (t < st) red[t] += red[t + st];
        __syncthreads();
    }
    if (t == 0) { Z[i] = red[0]; sInv = 1.f / red[0]; }
    __syncthreads();
    if (writeAlpha) {
        float inv = sInv;
        float4* out4 = (float4*)(alpha + (size_t)i * NV);
#pragma unroll
        for (int q = 0; q < 8; q++) {
            int j = t * 4 + q * 1024;
            unsigned word = sw[j >> 5];
            int b = j & 31;
            float4 e4 = *(const float4*)(E + j);
            float4 o;
            o.x = ((word >> (b + 0)) & 1u) ? e4.x * inv : 0.f;
            o.y = ((word >> (b + 1)) & 1u) ? e4.y * inv : 0.f;
            o.z = ((word >> (b + 2)) & 1u) ? e4.z * inv : 0.f;
            o.w = ((word >> (b + 3)) & 1u) ? e4.w * inv : 0.f;
            out4[t + q * 256] = o;
        }
    }
}

// ---------------- out = elu(out_un / Z) -------------------------------------------
__global__ void elu_kernel(const float* __restrict__ outun, const float* __restrict__ Z,
                           float* __restrict__ out) {
    int idx = blockIdx.x * 256 + threadIdx.x;           // 8192*64 threads, 4 elems each
    int row = idx >> 6;
    int c   = (idx & 63) << 2;
    float inv = 1.f / Z[row];
    float4 v = *(const float4*)(outun + (size_t)row * OUTD + c);
    float4 o;
    float t0 = v.x * inv, t1 = v.y * inv, t2 = v.z * inv, t3 = v.w * inv;
    o.x = t0 > 0.f ? t0 : expm1f(t0);
    o.y = t1 > 0.f ? t1 : expm1f(t1);
    o.z = t2 > 0.f ? t2 : expm1f(t2);
    o.w = t3 > 0.f ? t3 : expm1f(t3);
    *(float4*)(out + (size_t)row * OUTD + c) = o;
}

// ---------------- launch -----------------------------------------------------------
extern "C" void kernel_launch(void* const* d_in, const int* in_sizes, int n_in,
                              void* d_out, int out_size) {
    const float* x   = (const float*)d_in[0];
    const int*   adj = (const int*)d_in[1];
    const float* W   = (const float*)d_in[2];
    const float* a   = (const float*)d_in[3];
    float* out = (float*)d_out;

    const long long ND = (long long)NV * OUTD;
    const long long NN = (long long)NV * NV;
    int wantOut = 1, wantAlpha = 1;
    float* alphaPtr = out;
    if ((long long)out_size >= ND + NN) {
        alphaPtr = out + ND;                  // (elu_out, alpha) concatenated
    } else if ((long long)out_size == NN) {
        wantOut = 0;                          // alpha only
    } else {
        wantAlpha = 0;                        // elu_out only
    }

    float *p_h, *p_s, *p_E, *p_Z, *p_m, *p_outun;
    unsigned short *p_A2x, *p_B2w, *p_G2;
    unsigned *p_mask;
    cudaGetSymbolAddress((void**)&p_h, g_h);
    cudaGetSymbolAddress((void**)&p_A2x, g_A2x);
    cudaGetSymbolAddress((void**)&p_B2w, g_B2w);
    cudaGetSymbolAddress((void**)&p_s, g_s);
    cudaGetSymbolAddress((void**)&p_E, g_E);
    cudaGetSymbolAddress((void**)&p_Z, g_Z);
    cudaGetSymbolAddress((void**)&p_m, g_m);
    cudaGetSymbolAddress((void**)&p_mask, g_mask);
    cudaGetSymbolAddress((void**)&p_G2, g_G2);
    cudaGetSymbolAddress((void**)&p_outun, g_outun);

    // 1) split x and W into double-bf16 layouts
    prep_x_kernel<<<4096, 256>>>(x, p_A2x);
    prep_w_kernel<<<512, 256>>>(W, p_B2w);
    // 2) h = x @ W^T  via bf16 mma, K'=1536 (xh*wh + xh*wl + xl*wh)
    gemm_bf16_kernel<false><<<dim3(4, 64), 256>>>(p_A2x, nullptr, p_B2w, p_h, 1536);
    // 3) s_j = h @ a[256:], global max for exp stability
    s_kernel<<<1024, 256>>>(p_h, a, p_s);
    max_kernel<<<1, 1024>>>(p_s, p_m);
    // 4) E = exp(s - m); G2 = double-bf16 of E*h (interleaved hi/lo rows)
    eg_kernel<<<2048, 256>>>(p_h, p_s, p_m, p_E, p_G2);
    // 5) single pass over adj: bitmask + Z_i + alpha (s_i cancels in softmax)
    alpha_kernel<<<NV, 256>>>(adj, p_E, p_mask, p_Z, alphaPtr, wantAlpha);
    // 6) out_un = adj_bits @ G2  (bf16 tensor GEMM, K'=16384, exact 0/1 A)
    gemm_bf16_kernel<true><<<dim3(4, 64), 256>>>(nullptr, p_mask, p_G2, p_outun, 16384);
    // 7) out = elu(out_un / Z)
    if (wantOut) elu_kernel<<<2048, 256>>>(p_outun, p_Z, out);
}

// round 8
// speedup vs baseline: 1.0007x; 1.0007x over previous
#include <cuda_runtime.h>
#include <cuda_bf16.h>
#include <math.h>

#define NV   8192
#define IND  512
#define OUTD 256

// ---------------- device scratch (no runtime allocation allowed) ----------------
__device__ float          g_h[NV * OUTD];                    // 8 MB
__device__ unsigned short g_A2x[(size_t)NV * 1536];          // 24 MB  (xh | xh | xl) bf16 bits
__device__ unsigned short g_B2w[1536 * OUTD];                // 0.75 MB (wh ; wl ; wh) bf16 bits
__device__ float          g_s[NV];
__device__ float          g_E[NV];
__device__ float          g_Z[NV];
__device__ float          g_m[1];
__device__ unsigned       g_mask[(size_t)NV * 256];          // 8 MB bitmask of adj
__device__ unsigned short g_G2[(size_t)2 * NV * OUTD];       // 8 MB  rows 2j=hi(E*h), 2j+1=lo
__device__ float          g_outun[NV * OUTD];                // 8 MB

__device__ __forceinline__ unsigned short f2bf(float f) {
    return __bfloat16_as_ushort(__float2bfloat16_rn(f));
}
__device__ __forceinline__ float bf2f(unsigned short u) {
    return __bfloat162float(__ushort_as_bfloat16(u));
}

// ---------------- prep: split x into (hi|hi|lo) row blocks of A2x -----------------
__global__ void prep_x_kernel(const float* __restrict__ x, unsigned short* __restrict__ A2x) {
    int idx = blockIdx.x * 256 + threadIdx.x;           // 8192*128 threads, 4 elems each
    int row = idx >> 7;
    int c   = (idx & 127) << 2;
    float4 v = *(const float4*)(x + (size_t)row * IND + c);
    unsigned short h0 = f2bf(v.x), h1 = f2bf(v.y), h2 = f2bf(v.z), h3 = f2bf(v.w);
    unsigned short l0 = f2bf(v.x - bf2f(h0)), l1 = f2bf(v.y - bf2f(h1));
    unsigned short l2 = f2bf(v.z - bf2f(h2)), l3 = f2bf(v.w - bf2f(h3));
    uint2 hp = make_uint2((unsigned)h0 | ((unsigned)h1 << 16), (unsigned)h2 | ((unsigned)h3 << 16));
    uint2 lp = make_uint2((unsigned)l0 | ((unsigned)l1 << 16), (unsigned)l2 | ((unsigned)l3 << 16));
    unsigned short* base = A2x + (size_t)row * 1536;
    *(uint2*)(base + c)        = hp;
    *(uint2*)(base + 512 + c)  = hp;
    *(uint2*)(base + 1024 + c) = lp;
}

// ---------------- prep: W [256,512] -> B2w [1536,256] = (wh ; wl ; wh) ------------
__global__ void prep_w_kernel(const float* __restrict__ W, unsigned short* __restrict__ B2w) {
    int idx = blockIdx.x * 256 + threadIdx.x;           // 131072 threads
    int n = idx >> 9;
    int k = idx & 511;
    float f = W[idx];
    unsigned short hi = f2bf(f);
    unsigned short lo = f2bf(f - bf2f(hi));
    B2w[(size_t)k * 256 + n]          = hi;
    B2w[(size_t)(512 + k) * 256 + n]  = lo;
    B2w[(size_t)(1024 + k) * 256 + n] = hi;
}

// ---------------- shared bf16 MMA GEMM: C[M,256] += A[M,K] * B[K,256] -------------
// BM=128, BN=64, BK=64, 256 threads (8 warps, 4x2), warp tile 32x32, mma m16n8k16.
// FROM_BITS: A generated from bitmask (bit j -> k'=2j and 2j+1, value 1.0bf16).
template <bool FROM_BITS>
__global__ void __launch_bounds__(256, 2)
gemm_bf16_kernel(const unsigned short* __restrict__ Ag,
                 const unsigned* __restrict__ Abits,
                 const unsigned short* __restrict__ Bg,
                 float* __restrict__ C, int K)
{
    __shared__ __align__(16) unsigned short sA[128][72];
    __shared__ __align__(16) unsigned short sB[64][72];

    const int tid  = threadIdx.x;
    const int lane = tid & 31;
    const int warp = tid >> 5;
    const int wm = warp & 3;         // 4 warps along M (32 rows each)
    const int wn = warp >> 2;        // 2 warps along N (32 cols each)
    const int m0 = blockIdx.y * 128;
    const int n0 = blockIdx.x * 64;

    float acc[2][4][4];
#pragma unroll
    for (int i = 0; i < 2; i++)
#pragma unroll
        for (int j = 0; j < 4; j++)
#pragma unroll
            for (int k = 0; k < 4; k++) acc[i][j][k] = 0.f;

    const int nIter = K >> 6;
    const int rowA = tid >> 3, segA = tid & 7;   // staging indices
    const int ar = tid >> 1, ah = tid & 1;       // bit-expansion indices

    unsigned pw = 0;
    uint4 pa0, pa1, pa2, pa3, pb0, pb1;

    // ---- prefetch kb = 0 ----
    {
        if (FROM_BITS) {
            pw = Abits[(size_t)(m0 + ar) * (K >> 6) + 0];
        } else {
            pa0 = *(const uint4*)(Ag + (size_t)(m0 + rowA)      * K + segA * 8);
            pa1 = *(const uint4*)(Ag + (size_t)(m0 + rowA + 32) * K + segA * 8);
            pa2 = *(const uint4*)(Ag + (size_t)(m0 + rowA + 64) * K + segA * 8);
            pa3 = *(const uint4*)(Ag + (size_t)(m0 + rowA + 96) * K + segA * 8);
        }
        pb0 = *(const uint4*)(Bg + (size_t)(rowA)      * 256 + n0 + segA * 8);
        pb1 = *(const uint4*)(Bg + (size_t)(rowA + 32) * 256 + n0 + segA * 8);
    }

    for (int kb = 0; kb < nIter; kb++) {
        // ---- store stage (regs -> smem) ----
        if (FROM_BITS) {
            unsigned w = pw >> (ah * 16);
            uint4* dst = (uint4*)&sA[ar][ah * 32];
#pragma unroll
            for (int q = 0; q < 4; q++) {
                uint4 v;
                v.x = (w & 1u) ? 0x3F803F80u : 0u; w >>= 1;
                v.y = (w & 1u) ? 0x3F803F80u : 0u; w >>= 1;
                v.z = (w & 1u) ? 0x3F803F80u : 0u; w >>= 1;
                v.w = (w & 1u) ? 0x3F803F80u : 0u; w >>= 1;
                dst[q] = v;
            }
        } else {
            *(uint4*)&sA[rowA][segA * 8]      = pa0;
            *(uint4*)&sA[rowA + 32][segA * 8] = pa1;
            *(uint4*)&sA[rowA + 64][segA * 8] = pa2;
            *(uint4*)&sA[rowA + 96][segA * 8] = pa3;
        }
        *(uint4*)&sB[rowA][segA * 8]      = pb0;
        *(uint4*)&sB[rowA + 32][segA * 8] = pb1;
        __syncthreads();

        // ---- prefetch kb+1 (overlaps with compute) ----
        if (kb + 1 < nIter) {
            int kn = kb + 1;
            if (FROM_BITS) {
                pw = Abits[(size_t)(m0 + ar) * (K >> 6) + kn];
            } else {
                pa0 = *(const uint4*)(Ag + (size_t)(m0 + rowA)      * K + kn * 64 + segA * 8);
                pa1 = *(const uint4*)(Ag + (size_t)(m0 + rowA + 32) * K + kn * 64 + segA * 8);
                pa2 = *(const uint4*)(Ag + (size_t)(m0 + rowA + 64) * K + kn * 64 + segA * 8);
                pa3 = *(const uint4*)(Ag + (size_t)(m0 + rowA + 96) * K + kn * 64 + segA * 8);
            }
            pb0 = *(const uint4*)(Bg + (size_t)(kn * 64 + rowA)      * 256 + n0 + segA * 8);
            pb1 = *(const uint4*)(Bg + (size_t)(kn * 64 + rowA + 32) * 256 + n0 + segA * 8);
        }

        // ---- compute ----
#pragma unroll
        for (int kk = 0; kk < 4; kk++) {
            unsigned a[2][4];
#pragma unroll
            for (int mi = 0; mi < 2; mi++) {
                int row = wm * 32 + mi * 16 + (lane >> 2);
                int col = kk * 16 + (lane & 3) * 2;
                a[mi][0] = *(const unsigned*)&sA[row][col];
                a[mi][1] = *(const unsigned*)&sA[row + 8][col];
                a[mi][2] = *(const unsigned*)&sA[row][col + 8];
                a[mi][3] = *(const unsigned*)&sA[row + 8][col + 8];
            }
            unsigned b[4][2];
#pragma unroll
            for (int ni = 0; ni < 4; ni++) {
                unsigned saddr = (unsigned)__cvta_generic_to_shared(
                    &sB[kk * 16 + (lane & 15)][wn * 32 + ni * 8]);
                asm volatile(
                    "ldmatrix.sync.aligned.m8n8.x2.trans.shared.b16 {%0,%1}, [%2];"
                    : "=r"(b[ni][0]), "=r"(b[ni][1]) : "r"(saddr));
            }
#pragma unroll
            for (int mi = 0; mi < 2; mi++)
#pragma unroll
                for (int ni = 0; ni < 4; ni++)
                    asm volatile(
                        "mma.sync.aligned.m16n8k16.row.col.f32.bf16.bf16.f32 "
                        "{%0,%1,%2,%3},{%4,%5,%6,%7},{%8,%9},{%0,%1,%2,%3};"
                        : "+f"(acc[mi][ni][0]), "+f"(acc[mi][ni][1]),
                          "+f"(acc[mi][ni][2]), "+f"(acc[mi][ni][3])
                        : "r"(a[mi][0]), "r"(a[mi][1]), "r"(a[mi][2]), "r"(a[mi][3]),
                          "r"(b[ni][0]), "r"(b[ni][1]));
        }
        __syncthreads();
    }

    // ---- epilogue ----
#pragma unroll
    for (int mi = 0; mi < 2; mi++) {
        int row = m0 + wm * 32 + mi * 16 + (lane >> 2);
#pragma unroll
        for (int ni = 0; ni < 4; ni++) {
            int col = n0 + wn * 32 + ni * 8 + (lane & 3) * 2;
            *(float2*)&C[(size_t)row * 256 + col]       = make_float2(acc[mi][ni][0], acc[mi][ni][1]);
            *(float2*)&C[(size_t)(row + 8) * 256 + col] = make_float2(acc[mi][ni][2], acc[mi][ni][3]);
        }
    }
}

// ---------------- s_j = h @ a[256:512] : one warp per row ------------------------
__global__ void s_kernel(const float* __restrict__ h, const float* __restrict__ a,
                         float* __restrict__ s) {
    int row  = blockIdx.x * 8 + (threadIdx.x >> 5);
    int lane = threadIdx.x & 31;
    const float* hr = h + (size_t)row * OUTD;
    const float* a2 = a + OUTD;
    float v = 0.f;
#pragma unroll
    for (int k = 0; k < 8; k++) v += hr[lane + 32 * k] * a2[lane + 32 * k];
#pragma unroll
    for (int off = 16; off; off >>= 1) v += __shfl_xor_sync(0xffffffffu, v, off);
    if (lane == 0) s[row] = v;
}

__global__ void max_kernel(const float* __restrict__ s, float* __restrict__ m) {
    __shared__ float red[1024];
    float v = -1e30f;
    for (int i = threadIdx.x; i < NV; i += 1024) v = fmaxf(v, s[i]);
    red[threadIdx.x] = v;
    __syncthreads();
    for (int st = 512; st; st >>= 1) {
        if (threadIdx.x < st) red[threadIdx.x] = fmaxf(red[threadIdx.x], red[threadIdx.x + st]);
        __syncthreads();
    }
    if (threadIdx.x == 0) *m = red[0];
}

// ---------------- E = exp(s-m); G2 rows 2j = bf16_hi(E*h), 2j+1 = bf16_lo ---------
__global__ void eg_kernel(const float* __restrict__ h, const float* __restrict__ s,
                          const float* __restrict__ m, float* __restrict__ E,
                          unsigned short* __restrict__ G2) {
    int idx = blockIdx.x * 256 + threadIdx.x;           // 8192*64 threads, 4 elems each
    int row = idx >> 6;
    int c   = (idx & 63) << 2;
    float e = expf(s[row] - *m);
    if ((idx & 63) == 0) E[row] = e;
    float4 hv = *(const float4*)(h + (size_t)row * OUTD + c);
    float g0 = e * hv.x, g1 = e * hv.y, g2 = e * hv.z, g3 = e * hv.w;
    unsigned short h0 = f2bf(g0), h1 = f2bf(g1), h2 = f2bf(g2), h3 = f2bf(g3);
    unsigned short l0 = f2bf(g0 - bf2f(h0)), l1 = f2bf(g1 - bf2f(h1));
    unsigned short l2 = f2bf(g2 - bf2f(h2)), l3 = f2bf(g3 - bf2f(h3));
    uint2 hp = make_uint2((unsigned)h0 | ((unsigned)h1 << 16), (unsigned)h2 | ((unsigned)h3 << 16));
    uint2 lp = make_uint2((unsigned)l0 | ((unsigned)l1 << 16), (unsigned)l2 | ((unsigned)l3 << 16));
    *(uint2*)(G2 + (size_t)(2 * row) * 256 + c)     = hp;
    *(uint2*)(G2 + (size_t)(2 * row + 1) * 256 + c) = lp;
}

// ---------------- per-row: bitmask, Z, alpha (adj read exactly once) --------------
__global__ void alpha_kernel(const int* __restrict__ adj, const float* __restrict__ E,
                             unsigned* __restrict__ mask, float* __restrict__ Z,
                             float* __restrict__ alpha, int writeAlpha) {
    __shared__ unsigned sw[256];
    __shared__ float red[256];
    __shared__ float sInv;
    const int i = blockIdx.x, t = threadIdx.x;
    const int4* row4 = (const int4*)(adj + (size_t)i * NV);
    float z = 0.f;
    unsigned w = 0;
    const int base = t * 8;                              // this thread owns j in [t*32, t*32+32)
#pragma unroll
    for (int q = 0; q < 8; q++) {
        int4 v = row4[base + q];
        float4 e4 = *(const float4*)(E + t * 32 + q * 4);
        if (v.x) { z += e4.x; w |= 1u << (q * 4 + 0); }
        if (v.y) { z += e4.y; w |= 1u << (q * 4 + 1); }
        if (v.z) { z += e4.z; w |= 1u << (q * 4 + 2); }
        if (v.w) { z += e4.w; w |= 1u << (q * 4 + 3); }
    }
    sw[t] = w;
    mask[(size_t)i * 256 + t] = w;
    red[t] = z;
    __syncthreads();
    for (int st = 128; st; st >>= 1) {
        if (t < st) red[t] += red[t + st];
        __syncthreads();
    }
    if (t == 0) { Z[i] = red[0]; sInv = 1.f / red[0]; }
    __syncthreads();
    if (writeAlpha) {
        float inv = sInv;
        float4* out4 = (float4*)(alpha + (size_t)i * NV);
#pragma unroll
        for (int q = 0; q < 8; q++) {
            int j = t * 4 + q * 1024;
            unsigned word = sw[j >> 5];
            int b = j & 31;
            float4 e4 = *(const float4*)(E + j);
            float4 o;
            o.x = ((word >> (b + 0)) & 1u) ? e4.x * inv : 0.f;
            o.y = ((word >> (b + 1)) & 1u) ? e4.y * inv : 0.f;
            o.z = ((word >> (b + 2)) & 1u) ? e4.z * inv : 0.f;
            o.w = ((word >> (b + 3)) & 1u) ? e4.w * inv : 0.f;
            out4[t + q * 256] = o;
        }
    }
}

// ---------------- out = elu(out_un / Z) -------------------------------------------
__global__ void elu_kernel(const float* __restrict__ outun, const float* __restrict__ Z,
                           float* __restrict__ out) {
    int idx = blockIdx.x * 256 + threadIdx.x;           // 8192*64 threads, 4 elems each
    int row = idx >> 6;
    int c   = (idx & 63) << 2;
    float inv = 1.f / Z[row];
    float4 v = *(const float4*)(outun + (size_t)row * OUTD + c);
    float4 o;
    float t0 = v.x * inv, t1 = v.y * inv, t2 = v.z * inv, t3 = v.w * inv;
    o.x = t0 > 0.f ? t0 : expm1f(t0);
    o.y = t1 > 0.f ? t1 : expm1f(t1);
    o.z = t2 > 0.f ? t2 : expm1f(t2);
    o.w = t3 > 0.f ? t3 : expm1f(t3);
    *(float4*)(out + (size_t)row * OUTD + c) = o;
}

// ---------------- launch -----------------------------------------------------------
extern "C" void kernel_launch(void* const* d_in, const int* in_sizes, int n_in,
                              void* d_out, int out_size) {
    const float* x   = (const float*)d_in[0];
    const int*   adj = (const int*)d_in[1];
    const float* W   = (const float*)d_in[2];
    const float* a   = (const float*)d_in[3];
    float* out = (float*)d_out;

    const long long ND = (long long)NV * OUTD;
    const long long NN = (long long)NV * NV;
    int wantOut = 1, wantAlpha = 1;
    float* alphaPtr = out;
    if ((long long)out_size >= ND + NN) {
        alphaPtr = out + ND;                  // (elu_out, alpha) concatenated
    } else if ((long long)out_size == NN) {
        wantOut = 0;                          // alpha only
    } else {
        wantAlpha = 0;                        // elu_out only
    }

    float *p_h, *p_s, *p_E, *p_Z, *p_m, *p_outun;
    unsigned short *p_A2x, *p_B2w, *p_G2;
    unsigned *p_mask;
    cudaGetSymbolAddress((void**)&p_h, g_h);
    cudaGetSymbolAddress((void**)&p_A2x, g_A2x);
    cudaGetSymbolAddress((void**)&p_B2w, g_B2w);
    cudaGetSymbolAddress((void**)&p_s, g_s);
    cudaGetSymbolAddress((void**)&p_E, g_E);
    cudaGetSymbolAddress((void**)&p_Z, g_Z);
    cudaGetSymbolAddress((void**)&p_m, g_m);
    cudaGetSymbolAddress((void**)&p_mask, g_mask);
    cudaGetSymbolAddress((void**)&p_G2, g_G2);
    cudaGetSymbolAddress((void**)&p_outun, g_outun);

    // 1) split x and W into double-bf16 layouts
    prep_x_kernel<<<4096, 256>>>(x, p_A2x);
    prep_w_kernel<<<512, 256>>>(W, p_B2w);
    // 2) h = x @ W^T  via bf16 mma, K'=1536 (xh*wh + xh*wl + xl*wh)
    gemm_bf16_kernel<false><<<dim3(4, 64), 256>>>(p_A2x, nullptr, p_B2w, p_h, 1536);
    // 3) s_j = h @ a[256:], global max for exp stability
    s_kernel<<<1024, 256>>>(p_h, a, p_s);
    max_kernel<<<1, 1024>>>(p_s, p_m);
    // 4) E = exp(s - m); G2 = double-bf16 of E*h (interleaved hi/lo rows)
    eg_kernel<<<2048, 256>>>(p_h, p_s, p_m, p_E, p_G2);
    // 5) single pass over adj: bitmask + Z_i + alpha (s_i cancels in softmax)
    alpha_kernel<<<NV, 256>>>(adj, p_E, p_mask, p_Z, alphaPtr, wantAlpha);
    // 6) out_un = adj_bits @ G2  (bf16 tensor GEMM, K'=16384, exact 0/1 A)
    gemm_bf16_kernel<true><<<dim3(4, 64), 256>>>(nullptr, p_mask, p_G2, p_outun, 16384);
    // 7) out = elu(out_un / Z)
    if (wantOut) elu_kernel<<<2048, 256>>>(p_outun, p_Z, out);
}